// round 16
// baseline (speedup 1.0000x reference)
#include <cuda_runtime.h>
#include <cuda_fp16.h>

#define N_NODES 100000
#define D 128
#define N_EDGES 1600000
#define ALLOC_BLK 98   // 98 * 1024 >= N_NODES

// Scratch (__device__ globals per allocation rules)
__device__ __half g_Yh[(size_t)N_NODES * D];              // x @ W, fp16 (25.6 MB)
__device__ int g_cnt[N_NODES];
__device__ int g_ptr[N_NODES];
__device__ int g_total;
__device__ uint4 g_equad[N_EDGES];                        // {src, dst, val_bits, 0}

// ---------------------------------------------------------------------------
// Zero output (own branch — only scatter depends on it)
// ---------------------------------------------------------------------------
__global__ void __launch_bounds__(256) zero_out_kernel(float4* __restrict__ z) {
    int i = blockIdx.x * 256 + threadIdx.x;
    z[i] = make_float4(0.f, 0.f, 0.f, 0.f);
}

// Zero histogram counters + allocator
__global__ void __launch_bounds__(256) zero_cnt_kernel() {
    int i = blockIdx.x * 256 + threadIdx.x;
    if (i < N_NODES) g_cnt[i] = 0;
    if (i == 0) g_total = 0;
}

// Histogram: 4 edges/thread (4 independent atomics -> MLP 4)
__global__ void __launch_bounds__(256) hist_kernel(const int4* __restrict__ dst4) {
    int i = blockIdx.x * 256 + threadIdx.x;
    if (i >= N_EDGES / 4) return;
    int4 d = dst4[i];
    atomicAdd(&g_cnt[d.x], 1);
    atomicAdd(&g_cnt[d.y], 1);
    atomicAdd(&g_cnt[d.z], 1);
    atomicAdd(&g_cnt[d.w], 1);
}

// ---------------------------------------------------------------------------
// One-pass offset allocation (PROVEN R13)
// ---------------------------------------------------------------------------
__global__ void __launch_bounds__(1024) alloc_kernel() {
    __shared__ int s[1024];
    __shared__ int base_sh;
    const int t = threadIdx.x;
    const int i = blockIdx.x * 1024 + t;

    int myv = (i < N_NODES) ? g_cnt[i] : 0;
    s[t] = myv;
    __syncthreads();

    for (int off = 1; off < 1024; off <<= 1) {
        int v = (t >= off) ? s[t - off] : 0;
        __syncthreads();
        s[t] += v;
        __syncthreads();
    }

    if (t == 1023) base_sh = atomicAdd(&g_total, s[1023]);
    __syncthreads();

    if (i < N_NODES) g_ptr[i] = base_sh + s[t] - myv;
}

// Place: 4 edges/thread, 4 independent cursor atomics in flight (MLP 4)
__global__ void __launch_bounds__(256) place_kernel(const int4*   __restrict__ src4,
                                                    const int4*   __restrict__ dst4,
                                                    const float4* __restrict__ val4) {
    int i = blockIdx.x * 256 + threadIdx.x;
    if (i >= N_EDGES / 4) return;
    int4   s = src4[i];
    int4   d = dst4[i];
    float4 v = val4[i];
    int p0 = atomicAdd(&g_ptr[d.x], 1);
    int p1 = atomicAdd(&g_ptr[d.y], 1);
    int p2 = atomicAdd(&g_ptr[d.z], 1);
    int p3 = atomicAdd(&g_ptr[d.w], 1);
    g_equad[p0] = make_uint4((unsigned)s.x, (unsigned)d.x, __float_as_uint(v.x), 0u);
    g_equad[p1] = make_uint4((unsigned)s.y, (unsigned)d.y, __float_as_uint(v.y), 0u);
    g_equad[p2] = make_uint4((unsigned)s.z, (unsigned)d.z, __float_as_uint(v.z), 0u);
    g_equad[p3] = make_uint4((unsigned)s.w, (unsigned)d.w, __float_as_uint(v.w), 0u);
}

// ---------------------------------------------------------------------------
// tf32 helpers
// ---------------------------------------------------------------------------
__device__ __forceinline__ unsigned f2tf32(float f) {
    unsigned r;
    asm("cvt.rna.tf32.f32 %0, %1;" : "=r"(r) : "f"(f));
    return r;
}

__device__ __forceinline__ void mma_tf32(float* d,
                                         unsigned a0, unsigned a1, unsigned a2, unsigned a3,
                                         unsigned b0, unsigned b1) {
    asm volatile(
        "mma.sync.aligned.m16n8k8.row.col.f32.tf32.tf32.f32 "
        "{%0,%1,%2,%3}, {%4,%5,%6,%7}, {%8,%9}, {%0,%1,%2,%3};"
        : "+f"(d[0]), "+f"(d[1]), "+f"(d[2]), "+f"(d[3])
        : "r"(a0), "r"(a1), "r"(a2), "r"(a3), "r"(b0), "r"(b1));
}

// ---------------------------------------------------------------------------
// Tensor-core GEMM R16: NO W smem tile. B fragments loaded directly from
// global via __ldg (W = 64KB, L1-resident; 4 sectors/warp-LDG) + explicit
// cvt to tf32. Kills the per-block 64KB W fill + halves smem (67.6KB)
// -> 2 blocks/SM, x-fill latency hidden across blocks.
// ---------------------------------------------------------------------------
#define WS_STRIDE 132
#define GEMM_ROWS 128
extern __shared__ unsigned gemm_smem[];   // xs[128*132] only

__global__ void __launch_bounds__(256) gemm_tc_kernel(const float* __restrict__ x,
                                                      const float* __restrict__ w) {
    unsigned* xs = gemm_smem;

    const int tid = threadIdx.x;
    const int row0 = blockIdx.x * GEMM_ROWS;

#pragma unroll
    for (int i = tid; i < GEMM_ROWS * 128; i += 256) {
        int r = i >> 7, c = i & 127;
        int gr = row0 + r;
        float xv = (gr < N_NODES) ? x[(size_t)gr * D + c] : 0.f;
        xs[r * WS_STRIDE + c] = f2tf32(xv);
    }
    __syncthreads();

    const int lane = tid & 31;
    const int warp = tid >> 5;
    const int g = lane >> 2;
    const int t = lane & 3;
    const int mw = (warp >> 1) * 32;
    const int nb = (warp & 1) * 64;

    float d[2][8][4];
#pragma unroll
    for (int mt = 0; mt < 2; mt++)
#pragma unroll
        for (int j = 0; j < 8; j++)
            d[mt][j][0] = d[mt][j][1] = d[mt][j][2] = d[mt][j][3] = 0.f;

#pragma unroll
    for (int k0 = 0; k0 < 128; k0 += 8) {
        unsigned a[2][4];
#pragma unroll
        for (int mt = 0; mt < 2; mt++) {
            int mr = mw + mt * 16;
            a[mt][0] = xs[(mr + g) * WS_STRIDE + k0 + t];
            a[mt][1] = xs[(mr + g + 8) * WS_STRIDE + k0 + t];
            a[mt][2] = xs[(mr + g) * WS_STRIDE + k0 + t + 4];
            a[mt][3] = xs[(mr + g + 8) * WS_STRIDE + k0 + t + 4];
        }
        const float* wr0 = w + (k0 + t) * D;
        const float* wr1 = w + (k0 + t + 4) * D;
#pragma unroll
        for (int j = 0; j < 8; j++) {
            int n0 = nb + j * 8;
            unsigned b0 = f2tf32(__ldg(wr0 + n0 + g));
            unsigned b1 = f2tf32(__ldg(wr1 + n0 + g));
            mma_tf32(d[0][j], a[0][0], a[0][1], a[0][2], a[0][3], b0, b1);
            mma_tf32(d[1][j], a[1][0], a[1][1], a[1][2], a[1][3], b0, b1);
        }
    }

    __half2* y2 = (__half2*)g_Yh;
#pragma unroll
    for (int mt = 0; mt < 2; mt++) {
        const int r0 = row0 + mw + mt * 16 + g;
        const int r1 = r0 + 8;
#pragma unroll
        for (int j = 0; j < 8; j++) {
            int n0 = nb + j * 8;
            if (r0 < N_NODES)
                y2[(size_t)r0 * 64 + (n0 >> 1) + t] =
                    __floats2half2_rn(d[mt][j][0], d[mt][j][1]);
            if (r1 < N_NODES)
                y2[(size_t)r1 * 64 + (n0 >> 1) + t] =
                    __floats2half2_rn(d[mt][j][2], d[mt][j][3]);
        }
    }
}

// ---------------------------------------------------------------------------
// Sorted-run scatter (PROVEN R9/R12)
// ---------------------------------------------------------------------------
__device__ __forceinline__ void red_add_v4(float* ptr, float a, float b,
                                           float c, float d) {
    asm volatile("red.global.add.v4.f32 [%0], {%1, %2, %3, %4};"
                 :: "l"(ptr), "f"(a), "f"(b), "f"(c), "f"(d)
                 : "memory");
}

__global__ void __launch_bounds__(256) scatter_sorted_kernel(float* __restrict__ z) {
    const int warp_id = (blockIdx.x * 256 + threadIdx.x) >> 5;
    const int lane = threadIdx.x & 31;
    const int base = warp_id * 32;

    uint4 q = g_equad[base + lane];
    unsigned plo = q.x;
    int      dstv = (int)q.y;
    unsigned phi = q.z;

    const uint2* Y2 = (const uint2*)g_Yh;

    float4 acc = make_float4(0.f, 0.f, 0.f, 0.f);
    int cur = __shfl_sync(0xffffffffu, dstv, 0);

#pragma unroll
    for (int grp = 0; grp < 4; grp++) {
        unsigned s[8];
        float    v[8];
        int      dd[8];
#pragma unroll
        for (int j = 0; j < 8; j++) {
            int sl = grp * 8 + j;
            s[j]  = __shfl_sync(0xffffffffu, plo, sl);
            v[j]  = __uint_as_float(__shfl_sync(0xffffffffu, phi, sl));
            dd[j] = __shfl_sync(0xffffffffu, dstv, sl);
        }
        uint2 r[8];
#pragma unroll
        for (int j = 0; j < 8; j++)
            r[j] = Y2[(size_t)s[j] * 32 + lane];

#pragma unroll
        for (int j = 0; j < 8; j++) {
            if (dd[j] != cur) {
                red_add_v4(z + (size_t)cur * D + lane * 4,
                           acc.x, acc.y, acc.z, acc.w);
                acc = make_float4(0.f, 0.f, 0.f, 0.f);
                cur = dd[j];
            }
            float2 a01 = __half22float2(*(const __half2*)&r[j].x);
            float2 a23 = __half22float2(*(const __half2*)&r[j].y);
            acc.x += v[j] * a01.x; acc.y += v[j] * a01.y;
            acc.z += v[j] * a23.x; acc.w += v[j] * a23.y;
        }
    }
    red_add_v4(z + (size_t)cur * D + lane * 4, acc.x, acc.y, acc.z, acc.w);
}

// ---------------------------------------------------------------------------
// Launch: 3-branch fork/join inside graph capture (streams/events created
// once; first call precedes the harness's pre-capture memory baseline).
// ---------------------------------------------------------------------------
extern "C" void kernel_launch(void* const* d_in, const int* in_sizes, int n_in,
                              void* d_out, int out_size) {
    const float* x   = (const float*)d_in[0];
    const float* w   = (const float*)d_in[1];
    const int*   src = (const int*)  d_in[2];
    const int*   dst = (const int*)  d_in[3];
    const float* val = (const float*)d_in[4];
    float*       z   = (float*)d_out;

    const int smem_bytes = (GEMM_ROWS * WS_STRIDE) * 4;   // 67584

    static cudaStream_t sA = nullptr, sB = nullptr;
    static cudaEvent_t evRoot = nullptr, evA = nullptr, evB = nullptr;
    if (sA == nullptr) {
        cudaFuncSetAttribute(gemm_tc_kernel,
                             cudaFuncAttributeMaxDynamicSharedMemorySize, smem_bytes);
        cudaStreamCreateWithFlags(&sA, cudaStreamNonBlocking);
        cudaStreamCreateWithFlags(&sB, cudaStreamNonBlocking);
        cudaEventCreateWithFlags(&evRoot, cudaEventDisableTiming);
        cudaEventCreateWithFlags(&evA, cudaEventDisableTiming);
        cudaEventCreateWithFlags(&evB, cudaEventDisableTiming);
    }

    // Fork
    cudaEventRecord(evRoot, 0);
    cudaStreamWaitEvent(sA, evRoot, 0);
    cudaStreamWaitEvent(sB, evRoot, 0);

    // Branch A: GEMM
    gemm_tc_kernel<<<(N_NODES + GEMM_ROWS - 1) / GEMM_ROWS, 256, smem_bytes, sA>>>(x, w);
    cudaEventRecord(evA, sA);

    // Branch B: zero output
    zero_out_kernel<<<(N_NODES * D / 4) / 256, 256, 0, sB>>>((float4*)z);
    cudaEventRecord(evB, sB);

    // Main branch: sort pipeline
    zero_cnt_kernel<<<(N_NODES + 255) / 256, 256>>>();
    hist_kernel<<<(N_EDGES / 4 + 255) / 256, 256>>>((const int4*)dst);
    alloc_kernel<<<ALLOC_BLK, 1024>>>();
    place_kernel<<<(N_EDGES / 4 + 255) / 256, 256>>>((const int4*)src, (const int4*)dst,
                                                     (const float4*)val);

    // Join
    cudaStreamWaitEvent(0, evA, 0);
    cudaStreamWaitEvent(0, evB, 0);
    scatter_sorted_kernel<<<(N_EDGES / 32) / 8, 256>>>(z);
}

// round 17
// speedup vs baseline: 1.0143x; 1.0143x over previous
#include <cuda_runtime.h>
#include <cuda_fp16.h>

#define N_NODES 100000
#define D 128
#define N_EDGES 1600000
#define ALLOC_BLK 98   // 98 * 1024 >= N_NODES

// Scratch (__device__ globals per allocation rules)
__device__ __half g_Yh[(size_t)N_NODES * D];              // x @ W, fp16 (25.6 MB)
__device__ int g_cnt[N_NODES];
__device__ int g_ptr[N_NODES];
__device__ int g_total;
__device__ uint4 g_equad[N_EDGES];                        // {src, dst, val_bits, 0}

// ---------------------------------------------------------------------------
__global__ void __launch_bounds__(256) zero_out_kernel(float4* __restrict__ z) {
    int i = blockIdx.x * 256 + threadIdx.x;
    z[i] = make_float4(0.f, 0.f, 0.f, 0.f);
}

__global__ void __launch_bounds__(256) zero_cnt_kernel() {
    int i = blockIdx.x * 256 + threadIdx.x;
    if (i < N_NODES) g_cnt[i] = 0;
    if (i == 0) g_total = 0;
}

// Histogram: 2 edges/thread (PROVEN R15)
__global__ void __launch_bounds__(256) hist_kernel(const int2* __restrict__ dst2) {
    int i = blockIdx.x * 256 + threadIdx.x;      // < N_EDGES/2
    int2 d = dst2[i];
    atomicAdd(&g_cnt[d.x], 1);
    atomicAdd(&g_cnt[d.y], 1);
}

// One-pass offset allocation (PROVEN R13)
__global__ void __launch_bounds__(1024) alloc_kernel() {
    __shared__ int s[1024];
    __shared__ int base_sh;
    const int t = threadIdx.x;
    const int i = blockIdx.x * 1024 + t;

    int myv = (i < N_NODES) ? g_cnt[i] : 0;
    s[t] = myv;
    __syncthreads();

    for (int off = 1; off < 1024; off <<= 1) {
        int v = (t >= off) ? s[t - off] : 0;
        __syncthreads();
        s[t] += v;
        __syncthreads();
    }

    if (t == 1023) base_sh = atomicAdd(&g_total, s[1023]);
    __syncthreads();

    if (i < N_NODES) g_ptr[i] = base_sh + s[t] - myv;
}

// Place: 2 edges/thread (PROVEN R15)
__global__ void __launch_bounds__(256) place_kernel(const int2*   __restrict__ src2,
                                                    const int2*   __restrict__ dst2,
                                                    const float2* __restrict__ val2) {
    int i = blockIdx.x * 256 + threadIdx.x;      // < N_EDGES/2
    int2   s = src2[i];
    int2   d = dst2[i];
    float2 v = val2[i];
    int p0 = atomicAdd(&g_ptr[d.x], 1);
    int p1 = atomicAdd(&g_ptr[d.y], 1);
    g_equad[p0] = make_uint4((unsigned)s.x, (unsigned)d.x, __float_as_uint(v.x), 0u);
    g_equad[p1] = make_uint4((unsigned)s.y, (unsigned)d.y, __float_as_uint(v.y), 0u);
}

// ---------------------------------------------------------------------------
// tf32 helpers
// ---------------------------------------------------------------------------
__device__ __forceinline__ unsigned f2tf32(float f) {
    unsigned r;
    asm("cvt.rna.tf32.f32 %0, %1;" : "=r"(r) : "f"(f));
    return r;
}

__device__ __forceinline__ void mma_tf32(float* d,
                                         unsigned a0, unsigned a1, unsigned a2, unsigned a3,
                                         unsigned b0, unsigned b1) {
    asm volatile(
        "mma.sync.aligned.m16n8k8.row.col.f32.tf32.tf32.f32 "
        "{%0,%1,%2,%3}, {%4,%5,%6,%7}, {%8,%9}, {%0,%1,%2,%3};"
        : "+f"(d[0]), "+f"(d[1]), "+f"(d[2]), "+f"(d[3])
        : "r"(a0), "r"(a1), "r"(a2), "r"(a3), "r"(b0), "r"(b1));
}

// ---------------------------------------------------------------------------
// Tensor-core GEMM (PROVEN R10/R15): W smem tile, 128 rows/block,
// m32 x n64 per warp.
// ---------------------------------------------------------------------------
#define WS_STRIDE 132
#define GEMM_ROWS 128
extern __shared__ unsigned gemm_smem[];

__global__ void __launch_bounds__(256) gemm_tc_kernel(const float* __restrict__ x,
                                                      const float* __restrict__ w) {
    unsigned* ws = gemm_smem;
    unsigned* xs = gemm_smem + 128 * WS_STRIDE;

    const int tid = threadIdx.x;
    const int row0 = blockIdx.x * GEMM_ROWS;

#pragma unroll
    for (int i = tid; i < 128 * 128; i += 256) {
        int k = i >> 7, n = i & 127;
        ws[k * WS_STRIDE + n] = f2tf32(w[i]);
    }
#pragma unroll
    for (int i = tid; i < GEMM_ROWS * 128; i += 256) {
        int r = i >> 7, c = i & 127;
        int gr = row0 + r;
        float xv = (gr < N_NODES) ? x[(size_t)gr * D + c] : 0.f;
        xs[r * WS_STRIDE + c] = f2tf32(xv);
    }
    __syncthreads();

    const int lane = tid & 31;
    const int warp = tid >> 5;
    const int g = lane >> 2;
    const int t = lane & 3;
    const int mw = (warp >> 1) * 32;
    const int nb = (warp & 1) * 64;

    float d[2][8][4];
#pragma unroll
    for (int mt = 0; mt < 2; mt++)
#pragma unroll
        for (int j = 0; j < 8; j++)
            d[mt][j][0] = d[mt][j][1] = d[mt][j][2] = d[mt][j][3] = 0.f;

#pragma unroll
    for (int k0 = 0; k0 < 128; k0 += 8) {
        unsigned a[2][4];
#pragma unroll
        for (int mt = 0; mt < 2; mt++) {
            int mr = mw + mt * 16;
            a[mt][0] = xs[(mr + g) * WS_STRIDE + k0 + t];
            a[mt][1] = xs[(mr + g + 8) * WS_STRIDE + k0 + t];
            a[mt][2] = xs[(mr + g) * WS_STRIDE + k0 + t + 4];
            a[mt][3] = xs[(mr + g + 8) * WS_STRIDE + k0 + t + 4];
        }
#pragma unroll
        for (int j = 0; j < 8; j++) {
            int n0 = nb + j * 8;
            unsigned b0 = ws[(k0 + t) * WS_STRIDE + n0 + g];
            unsigned b1 = ws[(k0 + t + 4) * WS_STRIDE + n0 + g];
            mma_tf32(d[0][j], a[0][0], a[0][1], a[0][2], a[0][3], b0, b1);
            mma_tf32(d[1][j], a[1][0], a[1][1], a[1][2], a[1][3], b0, b1);
        }
    }

    __half2* y2 = (__half2*)g_Yh;
#pragma unroll
    for (int mt = 0; mt < 2; mt++) {
        const int r0 = row0 + mw + mt * 16 + g;
        const int r1 = r0 + 8;
#pragma unroll
        for (int j = 0; j < 8; j++) {
            int n0 = nb + j * 8;
            if (r0 < N_NODES)
                y2[(size_t)r0 * 64 + (n0 >> 1) + t] =
                    __floats2half2_rn(d[mt][j][0], d[mt][j][1]);
            if (r1 < N_NODES)
                y2[(size_t)r1 * 64 + (n0 >> 1) + t] =
                    __floats2half2_rn(d[mt][j][2], d[mt][j][3]);
        }
    }
}

// ---------------------------------------------------------------------------
// Sorted-run scatter R17: 16-row prefetch (MLP=16, was 8). Two outer
// iterations; within each, all 16 Y-row loads issue back-to-back before any
// accumulate. Flush logic identical (per-edge sequential) -> same sums.
// ---------------------------------------------------------------------------
__device__ __forceinline__ void red_add_v4(float* ptr, float a, float b,
                                           float c, float d) {
    asm volatile("red.global.add.v4.f32 [%0], {%1, %2, %3, %4};"
                 :: "l"(ptr), "f"(a), "f"(b), "f"(c), "f"(d)
                 : "memory");
}

__global__ void __launch_bounds__(256) scatter_sorted_kernel(float* __restrict__ z) {
    const int warp_id = (blockIdx.x * 256 + threadIdx.x) >> 5;
    const int lane = threadIdx.x & 31;
    const int base = warp_id * 32;

    uint4 q = g_equad[base + lane];
    unsigned plo = q.x;
    int      dstv = (int)q.y;
    unsigned phi = q.z;

    const uint2* Y2 = (const uint2*)g_Yh;

    float4 acc = make_float4(0.f, 0.f, 0.f, 0.f);
    int cur = __shfl_sync(0xffffffffu, dstv, 0);

#pragma unroll
    for (int grp = 0; grp < 2; grp++) {
        // 16 source ids via shfl (no memory), then 16 independent loads.
        unsigned s[16];
#pragma unroll
        for (int j = 0; j < 16; j++)
            s[j] = __shfl_sync(0xffffffffu, plo, grp * 16 + j);

        uint2 r[16];
#pragma unroll
        for (int j = 0; j < 16; j++)
            r[j] = Y2[(size_t)s[j] * 32 + lane];

#pragma unroll
        for (int j = 0; j < 16; j++) {
            int   sl = grp * 16 + j;
            float v  = __uint_as_float(__shfl_sync(0xffffffffu, phi, sl));
            int   dd = __shfl_sync(0xffffffffu, dstv, sl);
            if (dd != cur) {
                red_add_v4(z + (size_t)cur * D + lane * 4,
                           acc.x, acc.y, acc.z, acc.w);
                acc = make_float4(0.f, 0.f, 0.f, 0.f);
                cur = dd;
            }
            float2 a01 = __half22float2(*(const __half2*)&r[j].x);
            float2 a23 = __half22float2(*(const __half2*)&r[j].y);
            acc.x += v * a01.x; acc.y += v * a01.y;
            acc.z += v * a23.x; acc.w += v * a23.y;
        }
    }
    red_add_v4(z + (size_t)cur * D + lane * 4, acc.x, acc.y, acc.z, acc.w);
}

// ---------------------------------------------------------------------------
// Launch: 3-branch fork/join inside graph capture (streams/events created
// once; first call precedes the harness's pre-capture memory baseline).
// ---------------------------------------------------------------------------
extern "C" void kernel_launch(void* const* d_in, const int* in_sizes, int n_in,
                              void* d_out, int out_size) {
    const float* x   = (const float*)d_in[0];
    const float* w   = (const float*)d_in[1];
    const int*   src = (const int*)  d_in[2];
    const int*   dst = (const int*)  d_in[3];
    const float* val = (const float*)d_in[4];
    float*       z   = (float*)d_out;

    const int smem_bytes = (128 * WS_STRIDE + GEMM_ROWS * WS_STRIDE) * 4;  // 135168

    static cudaStream_t sA = nullptr, sB = nullptr;
    static cudaEvent_t evRoot = nullptr, evA = nullptr, evB = nullptr;
    if (sA == nullptr) {
        cudaFuncSetAttribute(gemm_tc_kernel,
                             cudaFuncAttributeMaxDynamicSharedMemorySize, smem_bytes);
        cudaStreamCreateWithFlags(&sA, cudaStreamNonBlocking);
        cudaStreamCreateWithFlags(&sB, cudaStreamNonBlocking);
        cudaEventCreateWithFlags(&evRoot, cudaEventDisableTiming);
        cudaEventCreateWithFlags(&evA, cudaEventDisableTiming);
        cudaEventCreateWithFlags(&evB, cudaEventDisableTiming);
    }

    // Fork
    cudaEventRecord(evRoot, 0);
    cudaStreamWaitEvent(sA, evRoot, 0);
    cudaStreamWaitEvent(sB, evRoot, 0);

    // Branch A: GEMM
    gemm_tc_kernel<<<(N_NODES + GEMM_ROWS - 1) / GEMM_ROWS, 256, smem_bytes, sA>>>(x, w);
    cudaEventRecord(evA, sA);

    // Branch B: zero output
    zero_out_kernel<<<(N_NODES * D / 4) / 256, 256, 0, sB>>>((float4*)z);
    cudaEventRecord(evB, sB);

    // Main branch: sort pipeline
    zero_cnt_kernel<<<(N_NODES + 255) / 256, 256>>>();
    hist_kernel<<<(N_EDGES / 2) / 256, 256>>>((const int2*)dst);
    alloc_kernel<<<ALLOC_BLK, 1024>>>();
    place_kernel<<<(N_EDGES / 2) / 256, 256>>>((const int2*)src, (const int2*)dst,
                                               (const float2*)val);

    // Join
    cudaStreamWaitEvent(0, evA, 0);
    cudaStreamWaitEvent(0, evB, 0);
    scatter_sorted_kernel<<<(N_EDGES / 32) / 8, 256>>>(z);
}